// round 4
// baseline (speedup 1.0000x reference)
#include <cuda_runtime.h>

// QConv2d: new_rho[b] = V * rho[b] * V^T, V = uc[:,2:4] (x) ux (x) uy.
// Mode-product formulation, one 128x132 f32 smem tile per batch, 256 blocks.
//   P1: gmem load fused with j-col contraction (uy), write smem (STS.128)
//   P2: j-row contraction (uy, same regs)   -- column walk, conflict-free
//   P3: i-col contraction (ux)              -- stride-8, LANE-REMAPPED so all
//       32 lanes hit distinct banks (bank = 8*((rl+i)&3) + 4*rb + qj)
//   P4: i-row contraction (ux)              -- column walk, conflict-free
//   P5: channel expansion uc[:,2:4] both sides -> gmem; LANE-REMAPPED so the
//       four LDS.128 per task are conflict-free (quad = plow + q4 + 16*pl)
// All contractions use packed fma.rn.f32x2. All smem accesses conflict-free.

#define SROW 132
typedef unsigned long long ull;

__device__ __forceinline__ ull pk2(float lo, float hi) {
    ull r; asm("mov.b64 %0, {%1,%2};" : "=l"(r) : "f"(lo), "f"(hi)); return r;
}
__device__ __forceinline__ float2 upk(ull a) {
    float2 r; asm("mov.b64 {%0,%1}, %2;" : "=f"(r.x), "=f"(r.y) : "l"(a)); return r;
}
__device__ __forceinline__ ull ffma2(ull a, ull b, ull c) {
    ull d; asm("fma.rn.f32x2 %0, %1, %2, %3;" : "=l"(d) : "l"(a), "l"(b), "l"(c)); return d;
}
__device__ __forceinline__ ull fmul2(ull a, ull b) {
    ull d; asm("mul.rn.f32x2 %0, %1, %2;" : "=l"(d) : "l"(a), "l"(b)); return d;
}

// out[q] = sum_j m[q][j] * in[j], j-packed: m2[q*4+jp] = {m[q][2jp], m[q][2jp+1]}
__device__ __forceinline__ void contract8(const ull* m2, const ull* in2, float* out) {
    #pragma unroll
    for (int q = 0; q < 8; q++) {
        ull acc = fmul2(m2[q * 4 + 0], in2[0]);
        acc = ffma2(m2[q * 4 + 1], in2[1], acc);
        acc = ffma2(m2[q * 4 + 2], in2[2], acc);
        acc = ffma2(m2[q * 4 + 3], in2[3], acc);
        float2 a = upk(acc);
        out[q] = a.x + a.y;
    }
}

__global__ __launch_bounds__(256, 2)
void qconv_kernel(const float* __restrict__ rho_g,
                  const float* __restrict__ ux_g,
                  const float* __restrict__ uy_g,
                  const float* __restrict__ uc_g,
                  float* __restrict__ out_g)
{
    extern __shared__ float B[];  // [128][SROW]
    const int b = blockIdx.x;
    const int t = threadIdx.x;
    const float* rg = rho_g + (size_t)b * 16384;

    ull m2[32];
    const ull* uy2 = reinterpret_cast<const ull*>(uy_g);
    #pragma unroll
    for (int i = 0; i < 32; i++) m2[i] = __ldg(uy2 + i);

    // ---- P1: fused gmem load + j-col: B[r, f*64+i*8+q] = sum_j uy[q][j] rho[r, f*64+i*8+j]
    #pragma unroll
    for (int k = 0; k < 8; k++) {
        int g = t + 256 * k;          // (r, f*8+i)
        int r = g >> 4;
        int h = g & 15;
        const ulonglong2* src = reinterpret_cast<const ulonglong2*>(rg + r * 128 + h * 8);
        ulonglong2 v0 = __ldg(src);
        ulonglong2 v1 = __ldg(src + 1);
        ull in2[4] = {v0.x, v0.y, v1.x, v1.y};
        float o[8];
        contract8(m2, in2, o);
        float4* dst = reinterpret_cast<float4*>(&B[r * SROW + h * 8]);
        dst[0] = make_float4(o[0], o[1], o[2], o[3]);
        dst[1] = make_float4(o[4], o[5], o[6], o[7]);
    }
    __syncthreads();

    // ---- P2: j-row (uy in regs): thread owns a column, walks 8-row groups.
    // bank = (4j + col) % 32; lanes have 32 consecutive cols -> conflict-free.
    #pragma unroll
    for (int k = 0; k < 8; k++) {
        int task = t + 256 * k;       // (fi, col)
        int col  = task & 127;
        int fi   = task >> 7;
        float* p = &B[fi * 8 * SROW + col];
        float s[8];
        #pragma unroll
        for (int j = 0; j < 8; j++) s[j] = p[j * SROW];
        ull in2[4] = {pk2(s[0], s[1]), pk2(s[2], s[3]), pk2(s[4], s[5]), pk2(s[6], s[7])};
        float o[8];
        contract8(m2, in2, o);
        #pragma unroll
        for (int q = 0; q < 8; q++) p[q * SROW] = o[q];
    }

    const ull* ux2 = reinterpret_cast<const ull*>(ux_g);
    #pragma unroll
    for (int i = 0; i < 32; i++) m2[i] = __ldg(ux2 + i);
    __syncthreads();

    // ---- P3: i-col: cols f*64+i*8+qj, stride 8. Lane remap for distinct banks:
    // lane = (qj = t&7, rl = (t>>3)&3); r = 8*rh + 2*rl + rb.
    // bank(i) = (8*((rl+i)&3) + 4*rb + qj) % 32 -> 32 distinct per load. 
    #pragma unroll
    for (int k = 0; k < 8; k++) {
        int n  = t + 256 * k;
        int qj = n & 7;
        int rl = (n >> 3) & 3;
        int hi = n >> 5;              // 0..63
        int f  = hi & 1;
        int rb = (hi >> 1) & 1;
        int rh = hi >> 2;             // 0..15
        int r  = rh * 8 + rl * 2 + rb;
        float* p = &B[r * SROW + f * 64 + qj];
        float s[8];
        #pragma unroll
        for (int i = 0; i < 8; i++) s[i] = p[i * 8];
        ull in2[4] = {pk2(s[0], s[1]), pk2(s[2], s[3]), pk2(s[4], s[5]), pk2(s[6], s[7])};
        float o[8];
        contract8(m2, in2, o);
        #pragma unroll
        for (int q = 0; q < 8; q++) p[q * 8] = o[q];
    }
    __syncthreads();

    // ---- P4: i-row: thread owns a column, rows f*64+qj+8i, stride 8*SROW.
    // bank = (4qj + col) % 32; lanes have 32 consecutive cols -> conflict-free.
    #pragma unroll
    for (int k = 0; k < 8; k++) {
        int task = t + 256 * k;       // (fq, col)
        int col  = task & 127;
        int fq   = task >> 7;
        int f    = fq >> 3;
        int qj   = fq & 7;
        float* p = &B[(f * 64 + qj) * SROW + col];
        float s[8];
        #pragma unroll
        for (int i = 0; i < 8; i++) s[i] = p[i * 8 * SROW];
        ull in2[4] = {pk2(s[0], s[1]), pk2(s[2], s[3]), pk2(s[4], s[5]), pk2(s[6], s[7])};
        float o[8];
        contract8(m2, in2, o);
        #pragma unroll
        for (int q = 0; q < 8; q++) p[q * 8 * SROW] = o[q];
    }

    // ---- P5: out[c*64+p, c2*64+q] = sum_{f,f2} A[c][f] A[c2][f2] B[f*64+p, f2*64+q]
    ull Ad0[4], Ad1[4];
    #pragma unroll
    for (int c = 0; c < 4; c++) {
        float a0 = __ldg(uc_g + c * 4 + 2);
        float a1 = __ldg(uc_g + c * 4 + 3);
        Ad0[c] = pk2(a0, a0);
        Ad1[c] = pk2(a1, a1);
    }
    __syncthreads();

    // Lane remap: lane = (q4 = t&15, pl = (t>>4)&1); p = plow + 16*pl + 32*ph.
    // quad-bank = (plow + q4 + 16*pl) % 32 -> 32 distinct; stores stay 2x256B.
    float* og = out_g + (size_t)b * 65536;
    #pragma unroll
    for (int k = 0; k < 4; k++) {
        int e    = t + 256 * k;       // 1024 (p, q4) tasks
        int q4   = e & 15;
        int pl   = (e >> 4) & 1;
        int plow = (e >> 5) & 15;
        int ph   = (e >> 9) & 1;
        int p    = plow + 16 * pl + 32 * ph;   // 0..63
        ulonglong2 s00 = *reinterpret_cast<const ulonglong2*>(&B[p * SROW + q4 * 4]);
        ulonglong2 s01 = *reinterpret_cast<const ulonglong2*>(&B[p * SROW + 64 + q4 * 4]);
        ulonglong2 s10 = *reinterpret_cast<const ulonglong2*>(&B[(64 + p) * SROW + q4 * 4]);
        ulonglong2 s11 = *reinterpret_cast<const ulonglong2*>(&B[(64 + p) * SROW + 64 + q4 * 4]);
        #pragma unroll
        for (int c = 0; c < 4; c++) {
            ull t0a = ffma2(Ad0[c], s00.x, fmul2(Ad1[c], s10.x));
            ull t0b = ffma2(Ad0[c], s00.y, fmul2(Ad1[c], s10.y));
            ull t1a = ffma2(Ad0[c], s01.x, fmul2(Ad1[c], s11.x));
            ull t1b = ffma2(Ad0[c], s01.y, fmul2(Ad1[c], s11.y));
            #pragma unroll
            for (int c2 = 0; c2 < 4; c2++) {
                ull oa = ffma2(Ad0[c2], t0a, fmul2(Ad1[c2], t1a));
                ull ob = ffma2(Ad0[c2], t0b, fmul2(Ad1[c2], t1b));
                *reinterpret_cast<ulonglong2*>(og + (c * 64 + p) * 256 + c2 * 64 + q4 * 4) =
                    make_ulonglong2(oa, ob);
            }
        }
    }
}

extern "C" void kernel_launch(void* const* d_in, const int* in_sizes, int n_in,
                              void* d_out, int out_size)
{
    const float* rho = (const float*)d_in[0];
    const float* ux  = (const float*)d_in[1];
    const float* uy  = (const float*)d_in[2];
    const float* uc  = (const float*)d_in[3];
    float* out = (float*)d_out;

    const int smem_bytes = 128 * SROW * sizeof(float);  // 67584
    cudaFuncSetAttribute(qconv_kernel,
                         cudaFuncAttributeMaxDynamicSharedMemorySize, smem_bytes);
    qconv_kernel<<<256, 256, smem_bytes>>>(rho, ux, uy, uc, out);
}

// round 6
// speedup vs baseline: 1.1046x; 1.1046x over previous
#include <cuda_runtime.h>

// QConv2d: new_rho[b] = V rho[b] V^T, V = uc[:,2:4] (x) ux (x) uy.
// Register-resident fused mode products, one 128x132 f32 smem tile per batch:
//   A: thread owns (col, f-row-block): 64 coalesced LDG.32 down the column,
//      full kron(ux,uy) row-transform in registers, 64 scalar STS (conflict-free)
//   B: thread owns (row, f-col-block): 16 LDS.128 (conflict-free), same
//      transform on the column index in registers, 16 STS.128 back
//   C: channel expansion with uc[:,2:4] both sides -> gmem (lane-remapped,
//      conflict-free LDS.128 + coalesced STG.128)
// u-matrices live in __constant__ (freeing ~64 regs vs register-resident),
// copied via D2D cudaMemcpyToSymbolAsync (graph-capturable memcpy nodes).
// All 8-term contractions use packed fma.rn.f32x2.

#define SROW 132
typedef unsigned long long ull;

__constant__ ull   c_uy2[32];   // uy row-major, viewed as 32 f32-pairs
__constant__ ull   c_ux2[32];   // ux row-major, viewed as 32 f32-pairs
__constant__ float c_uc[16];    // uc row-major

__device__ __forceinline__ ull pk2(float lo, float hi) {
    ull r; asm("mov.b64 %0, {%1,%2};" : "=l"(r) : "f"(lo), "f"(hi)); return r;
}
__device__ __forceinline__ float2 upk(ull a) {
    float2 r; asm("mov.b64 {%0,%1}, %2;" : "=f"(r.x), "=f"(r.y) : "l"(a)); return r;
}
__device__ __forceinline__ ull ffma2(ull a, ull b, ull c) {
    ull d; asm("fma.rn.f32x2 %0, %1, %2, %3;" : "=l"(d) : "l"(a), "l"(b), "l"(c)); return d;
}
__device__ __forceinline__ ull fmul2(ull a, ull b) {
    ull d; asm("mul.rn.f32x2 %0, %1, %2;" : "=l"(d) : "l"(a), "l"(b)); return d;
}

// In-register v' = kron(ux, uy) * v on a 64-vector with layout p = i*8 + j.
//   j-step: per row i:   v[8i+q]  = sum_j uy[q][j] v[8i+j]
//   i-step: per col qj:  v[8q+qj] = sum_i ux[q][i] v[8i+qj]
__device__ __forceinline__ void transform64(float* v)
{
    #pragma unroll
    for (int i = 0; i < 8; i++) {
        float* p = v + 8 * i;
        ull d0 = pk2(p[0], p[1]), d1 = pk2(p[2], p[3]);
        ull d2 = pk2(p[4], p[5]), d3 = pk2(p[6], p[7]);
        float tmp[8];
        #pragma unroll
        for (int q = 0; q < 8; q++) {
            ull acc = fmul2(c_uy2[q * 4 + 0], d0);
            acc = ffma2(c_uy2[q * 4 + 1], d1, acc);
            acc = ffma2(c_uy2[q * 4 + 2], d2, acc);
            acc = ffma2(c_uy2[q * 4 + 3], d3, acc);
            float2 a = upk(acc);
            tmp[q] = a.x + a.y;
        }
        #pragma unroll
        for (int q = 0; q < 8; q++) p[q] = tmp[q];
    }
    #pragma unroll
    for (int qj = 0; qj < 8; qj++) {
        float* p = v + qj;
        ull d0 = pk2(p[0],  p[8]),  d1 = pk2(p[16], p[24]);
        ull d2 = pk2(p[32], p[40]), d3 = pk2(p[48], p[56]);
        float tmp[8];
        #pragma unroll
        for (int q = 0; q < 8; q++) {
            ull acc = fmul2(c_ux2[q * 4 + 0], d0);
            acc = ffma2(c_ux2[q * 4 + 1], d1, acc);
            acc = ffma2(c_ux2[q * 4 + 2], d2, acc);
            acc = ffma2(c_ux2[q * 4 + 3], d3, acc);
            float2 a = upk(acc);
            tmp[q] = a.x + a.y;
        }
        #pragma unroll
        for (int q = 0; q < 8; q++) p[q * 8] = tmp[q];
    }
}

__global__ __launch_bounds__(256, 2)
void qconv_kernel(const float* __restrict__ rho_g,
                  float* __restrict__ out_g)
{
    extern __shared__ float B[];  // [128][SROW]
    const int b = blockIdx.x;
    const int t = threadIdx.x;
    const float* rg = rho_g + (size_t)b * 16384;

    // ---- Phase A: row-mode transform, direct from gmem ----
    // thread owns (col = t&127, fr = t>>7): rows fr*64 + p, p = 0..63.
    {
        const int col = t & 127;
        const int fr  = t >> 7;
        const float* src = rg + (size_t)(fr * 64) * 128 + col;
        float v[64];
        #pragma unroll
        for (int p = 0; p < 64; p++) v[p] = __ldg(src + p * 128);
        transform64(v);
        float* dst = &B[(fr * 64) * SROW + col];
        #pragma unroll
        for (int p = 0; p < 64; p++) dst[p * SROW] = v[p];
    }
    __syncthreads();

    // ---- Phase B: col-mode transform, smem <-> registers ----
    // thread owns (r = t>>1, fc = t&1): cols fc*64 + 0..63 of row r.
    {
        const int r  = t >> 1;
        const int fc = t & 1;
        float v[64];
        float4* p4 = reinterpret_cast<float4*>(&B[r * SROW + fc * 64]);
        #pragma unroll
        for (int c = 0; c < 16; c++) {
            float4 x = p4[c];
            v[c * 4 + 0] = x.x; v[c * 4 + 1] = x.y;
            v[c * 4 + 2] = x.z; v[c * 4 + 3] = x.w;
        }
        transform64(v);
        #pragma unroll
        for (int c = 0; c < 16; c++)
            p4[c] = make_float4(v[c * 4 + 0], v[c * 4 + 1], v[c * 4 + 2], v[c * 4 + 3]);
    }

    // ---- Phase C: channel expansion with uc[:,2:4] on both sides ----
    ull Ad0[4], Ad1[4];
    #pragma unroll
    for (int c = 0; c < 4; c++) {
        float a0 = c_uc[c * 4 + 2];
        float a1 = c_uc[c * 4 + 3];
        Ad0[c] = pk2(a0, a0);
        Ad1[c] = pk2(a1, a1);
    }
    __syncthreads();

    // Lane remap: lane = (q4 = t&15, pl = (t>>4)&1); p = plow + 16*pl + 32*ph.
    // quad-bank = (plow + q4 + 16*pl) % 32 -> 32 distinct; stores 2x256B segs.
    float* og = out_g + (size_t)b * 65536;
    #pragma unroll
    for (int k = 0; k < 4; k++) {
        int e    = t + 256 * k;       // 1024 (p, q4) tasks
        int q4   = e & 15;
        int pl   = (e >> 4) & 1;
        int plow = (e >> 5) & 15;
        int ph   = (e >> 9) & 1;
        int p    = plow + 16 * pl + 32 * ph;   // 0..63
        ulonglong2 s00 = *reinterpret_cast<const ulonglong2*>(&B[p * SROW + q4 * 4]);
        ulonglong2 s01 = *reinterpret_cast<const ulonglong2*>(&B[p * SROW + 64 + q4 * 4]);
        ulonglong2 s10 = *reinterpret_cast<const ulonglong2*>(&B[(64 + p) * SROW + q4 * 4]);
        ulonglong2 s11 = *reinterpret_cast<const ulonglong2*>(&B[(64 + p) * SROW + 64 + q4 * 4]);
        #pragma unroll
        for (int c = 0; c < 4; c++) {
            ull t0a = ffma2(Ad0[c], s00.x, fmul2(Ad1[c], s10.x));
            ull t0b = ffma2(Ad0[c], s00.y, fmul2(Ad1[c], s10.y));
            ull t1a = ffma2(Ad0[c], s01.x, fmul2(Ad1[c], s11.x));
            ull t1b = ffma2(Ad0[c], s01.y, fmul2(Ad1[c], s11.y));
            #pragma unroll
            for (int c2 = 0; c2 < 4; c2++) {
                ull oa = ffma2(Ad0[c2], t0a, fmul2(Ad1[c2], t1a));
                ull ob = ffma2(Ad0[c2], t0b, fmul2(Ad1[c2], t1b));
                *reinterpret_cast<ulonglong2*>(og + (c * 64 + p) * 256 + c2 * 64 + q4 * 4) =
                    make_ulonglong2(oa, ob);
            }
        }
    }
}

extern "C" void kernel_launch(void* const* d_in, const int* in_sizes, int n_in,
                              void* d_out, int out_size)
{
    const float* rho = (const float*)d_in[0];
    const float* ux  = (const float*)d_in[1];
    const float* uy  = (const float*)d_in[2];
    const float* uc  = (const float*)d_in[3];
    float* out = (float*)d_out;

    // u matrices -> constant memory (D2D async memcpys, graph-capturable)
    cudaMemcpyToSymbolAsync(c_uy2, uy, 64 * sizeof(float), 0, cudaMemcpyDeviceToDevice);
    cudaMemcpyToSymbolAsync(c_ux2, ux, 64 * sizeof(float), 0, cudaMemcpyDeviceToDevice);
    cudaMemcpyToSymbolAsync(c_uc,  uc, 16 * sizeof(float), 0, cudaMemcpyDeviceToDevice);

    const int smem_bytes = 128 * SROW * sizeof(float);  // 67584
    cudaFuncSetAttribute(qconv_kernel,
                         cudaFuncAttributeMaxDynamicSharedMemorySize, smem_bytes);
    qconv_kernel<<<256, 256, smem_bytes>>>(rho, out);
}

// round 7
// speedup vs baseline: 1.1896x; 1.0769x over previous
#include <cuda_runtime.h>

// QConv2d: new_rho[b] = V * rho[b] * V^T, V = uc[:,2:4] (x) ux (x) uy.
// Mode-product formulation, one 128x132 f32 smem tile per batch, 256 blocks.
// R3 structure (best so far) with u-matrices moved to __constant__ memory:
// constant-bank FFMA operands free the 64 registers previously pinned by the
// packed u-matrix, letting ptxas overlap the 8 independent per-phase chains.
//   P1: gmem load fused with j-col contraction (uy), write smem (STS.128)
//   P2: j-row contraction (uy)              -- column walk, conflict-free
//   P3: i-col contraction (ux)              -- stride-8, lane-remapped
//   P4: i-row contraction (ux)              -- column walk, conflict-free
//   P5: channel expansion uc[:,2:4] both sides -> gmem (lane-remapped)
// All contractions use packed fma.rn.f32x2. All smem accesses conflict-free.

#define SROW 132
typedef unsigned long long ull;

__constant__ ull   c_uy2[32];   // uy row-major, 32 f32-pairs
__constant__ ull   c_ux2[32];   // ux row-major, 32 f32-pairs
__constant__ float c_uc[16];    // uc row-major

__device__ __forceinline__ ull pk2(float lo, float hi) {
    ull r; asm("mov.b64 %0, {%1,%2};" : "=l"(r) : "f"(lo), "f"(hi)); return r;
}
__device__ __forceinline__ float2 upk(ull a) {
    float2 r; asm("mov.b64 {%0,%1}, %2;" : "=f"(r.x), "=f"(r.y) : "l"(a)); return r;
}
__device__ __forceinline__ ull ffma2(ull a, ull b, ull c) {
    ull d; asm("fma.rn.f32x2 %0, %1, %2, %3;" : "=l"(d) : "l"(a), "l"(b), "l"(c)); return d;
}
__device__ __forceinline__ ull fmul2(ull a, ull b) {
    ull d; asm("mul.rn.f32x2 %0, %1, %2;" : "=l"(d) : "l"(a), "l"(b)); return d;
}

// out[q] = sum_j m[q][j] * in[j]; m2 is __constant__, j-packed in pairs.
__device__ __forceinline__ void contract8(const ull* m2, const ull* in2, float* out) {
    #pragma unroll
    for (int q = 0; q < 8; q++) {
        ull acc = fmul2(m2[q * 4 + 0], in2[0]);
        acc = ffma2(m2[q * 4 + 1], in2[1], acc);
        acc = ffma2(m2[q * 4 + 2], in2[2], acc);
        acc = ffma2(m2[q * 4 + 3], in2[3], acc);
        float2 a = upk(acc);
        out[q] = a.x + a.y;
    }
}

__global__ __launch_bounds__(256, 2)
void qconv_kernel(const float* __restrict__ rho_g,
                  float* __restrict__ out_g)
{
    extern __shared__ float B[];  // [128][SROW]
    const int b = blockIdx.x;
    const int t = threadIdx.x;
    const float* rg = rho_g + (size_t)b * 16384;

    // ---- P1: fused gmem load + j-col: B[r, f*64+i*8+q] = sum_j uy[q][j] rho[r, f*64+i*8+j]
    #pragma unroll
    for (int k = 0; k < 8; k++) {
        int g = t + 256 * k;          // (r, f*8+i)
        int r = g >> 4;
        int h = g & 15;
        const ulonglong2* src = reinterpret_cast<const ulonglong2*>(rg + r * 128 + h * 8);
        ulonglong2 v0 = __ldg(src);
        ulonglong2 v1 = __ldg(src + 1);
        ull in2[4] = {v0.x, v0.y, v1.x, v1.y};
        float o[8];
        contract8(c_uy2, in2, o);
        float4* dst = reinterpret_cast<float4*>(&B[r * SROW + h * 8]);
        dst[0] = make_float4(o[0], o[1], o[2], o[3]);
        dst[1] = make_float4(o[4], o[5], o[6], o[7]);
    }
    __syncthreads();

    // ---- P2: j-row: thread owns a column, walks 8-row groups (conflict-free)
    #pragma unroll
    for (int k = 0; k < 8; k++) {
        int task = t + 256 * k;       // (fi, col)
        int col  = task & 127;
        int fi   = task >> 7;
        float* p = &B[fi * 8 * SROW + col];
        float s[8];
        #pragma unroll
        for (int j = 0; j < 8; j++) s[j] = p[j * SROW];
        ull in2[4] = {pk2(s[0], s[1]), pk2(s[2], s[3]), pk2(s[4], s[5]), pk2(s[6], s[7])};
        float o[8];
        contract8(c_uy2, in2, o);
        #pragma unroll
        for (int q = 0; q < 8; q++) p[q * SROW] = o[q];
    }
    __syncthreads();

    // ---- P3: i-col: cols f*64+i*8+qj, stride 8; lane remap for distinct banks:
    // lane = (qj = t&7, rl = (t>>3)&3); r = 8*rh + 2*rl + rb.
    // bank(i) = (8*((rl+i)&3) + 4*rb + qj) % 32 -> 32 distinct per load.
    #pragma unroll
    for (int k = 0; k < 8; k++) {
        int n  = t + 256 * k;
        int qj = n & 7;
        int rl = (n >> 3) & 3;
        int hi = n >> 5;              // 0..63
        int f  = hi & 1;
        int rb = (hi >> 1) & 1;
        int rh = hi >> 2;             // 0..15
        int r  = rh * 8 + rl * 2 + rb;
        float* p = &B[r * SROW + f * 64 + qj];
        float s[8];
        #pragma unroll
        for (int i = 0; i < 8; i++) s[i] = p[i * 8];
        ull in2[4] = {pk2(s[0], s[1]), pk2(s[2], s[3]), pk2(s[4], s[5]), pk2(s[6], s[7])};
        float o[8];
        contract8(c_ux2, in2, o);
        #pragma unroll
        for (int q = 0; q < 8; q++) p[q * 8] = o[q];
    }
    __syncthreads();

    // ---- P4: i-row: thread owns a column, rows f*64+qj+8i (conflict-free)
    #pragma unroll
    for (int k = 0; k < 8; k++) {
        int task = t + 256 * k;       // (fq, col)
        int col  = task & 127;
        int fq   = task >> 7;
        int f    = fq >> 3;
        int qj   = fq & 7;
        float* p = &B[(f * 64 + qj) * SROW + col];
        float s[8];
        #pragma unroll
        for (int i = 0; i < 8; i++) s[i] = p[i * 8 * SROW];
        ull in2[4] = {pk2(s[0], s[1]), pk2(s[2], s[3]), pk2(s[4], s[5]), pk2(s[6], s[7])};
        float o[8];
        contract8(c_ux2, in2, o);
        #pragma unroll
        for (int q = 0; q < 8; q++) p[q * 8 * SROW] = o[q];
    }

    // ---- P5: out[c*64+p, c2*64+q] = sum_{f,f2} A[c][f] A[c2][f2] B[f*64+p, f2*64+q]
    ull Ad0[4], Ad1[4];
    #pragma unroll
    for (int c = 0; c < 4; c++) {
        float a0 = c_uc[c * 4 + 2];
        float a1 = c_uc[c * 4 + 3];
        Ad0[c] = pk2(a0, a0);
        Ad1[c] = pk2(a1, a1);
    }
    __syncthreads();

    // Lane remap: lane = (q4 = t&15, pl = (t>>4)&1); p = plow + 16*pl + 32*ph.
    // quad-bank = (plow + q4 + 16*pl) % 32 -> 32 distinct; stores 2x256B segs.
    float* og = out_g + (size_t)b * 65536;
    #pragma unroll
    for (int k = 0; k < 4; k++) {
        int e    = t + 256 * k;       // 1024 (p, q4) tasks
        int q4   = e & 15;
        int pl   = (e >> 4) & 1;
        int plow = (e >> 5) & 15;
        int ph   = (e >> 9) & 1;
        int p    = plow + 16 * pl + 32 * ph;   // 0..63
        ulonglong2 s00 = *reinterpret_cast<const ulonglong2*>(&B[p * SROW + q4 * 4]);
        ulonglong2 s01 = *reinterpret_cast<const ulonglong2*>(&B[p * SROW + 64 + q4 * 4]);
        ulonglong2 s10 = *reinterpret_cast<const ulonglong2*>(&B[(64 + p) * SROW + q4 * 4]);
        ulonglong2 s11 = *reinterpret_cast<const ulonglong2*>(&B[(64 + p) * SROW + 64 + q4 * 4]);
        #pragma unroll
        for (int c = 0; c < 4; c++) {
            ull t0a = ffma2(Ad0[c], s00.x, fmul2(Ad1[c], s10.x));
            ull t0b = ffma2(Ad0[c], s00.y, fmul2(Ad1[c], s10.y));
            ull t1a = ffma2(Ad0[c], s01.x, fmul2(Ad1[c], s11.x));
            ull t1b = ffma2(Ad0[c], s01.y, fmul2(Ad1[c], s11.y));
            #pragma unroll
            for (int c2 = 0; c2 < 4; c2++) {
                ull oa = ffma2(Ad0[c2], t0a, fmul2(Ad1[c2], t1a));
                ull ob = ffma2(Ad0[c2], t0b, fmul2(Ad1[c2], t1b));
                *reinterpret_cast<ulonglong2*>(og + (c * 64 + p) * 256 + c2 * 64 + q4 * 4) =
                    make_ulonglong2(oa, ob);
            }
        }
    }
}

extern "C" void kernel_launch(void* const* d_in, const int* in_sizes, int n_in,
                              void* d_out, int out_size)
{
    const float* rho = (const float*)d_in[0];
    const float* ux  = (const float*)d_in[1];
    const float* uy  = (const float*)d_in[2];
    const float* uc  = (const float*)d_in[3];
    float* out = (float*)d_out;

    // u matrices -> constant memory (D2D async memcpys, graph-capturable)
    cudaMemcpyToSymbolAsync(c_uy2, uy, 64 * sizeof(float), 0, cudaMemcpyDeviceToDevice);
    cudaMemcpyToSymbolAsync(c_ux2, ux, 64 * sizeof(float), 0, cudaMemcpyDeviceToDevice);
    cudaMemcpyToSymbolAsync(c_uc,  uc, 16 * sizeof(float), 0, cudaMemcpyDeviceToDevice);

    const int smem_bytes = 128 * SROW * sizeof(float);  // 67584
    cudaFuncSetAttribute(qconv_kernel,
                         cudaFuncAttributeMaxDynamicSharedMemorySize, smem_bytes);
    qconv_kernel<<<256, 256, smem_bytes>>>(rho, out);
}